// round 1
// baseline (speedup 1.0000x reference)
#include <cuda_runtime.h>
#include <cuda_bf16.h>
#include <math.h>

// Problem constants
#define Bsz   2
#define Sseq  2048
#define HIDD  1024
#define Hh    16
#define NBQ   32
#define KSEL  8
#define BLK   64
#define Dd    64

// Blocked scratch: (B, H, NBQ, BLK, D)
#define QKV_ELEMS (Bsz * Hh * NBQ * BLK * Dd)   // 4,194,304
__device__ float g_q[QKV_ELEMS];
__device__ float g_k[QKV_ELEMS];
__device__ float g_v[QKV_ELEMS];

// ---------------------------------------------------------------------------
// QKV projection GEMM: C(4096x1024) = X(4096x1024) @ W(1024x1024) + bias
// Output written into blocked (B,H,NBQ,BLK,D) layout.
// BM=BN=64, BK=16, 256 threads, 4x4 micro-tile per thread.
// gridDim.z selects {q,k,v}.
// ---------------------------------------------------------------------------
#define GBM 64
#define GBN 64
#define GBK 16

__global__ __launch_bounds__(256)
void qkv_kernel(const float* __restrict__ X,
                const float* __restrict__ Wq, const float* __restrict__ bq,
                const float* __restrict__ Wk, const float* __restrict__ bk,
                const float* __restrict__ Wv, const float* __restrict__ bv)
{
    const float* W;
    const float* bias;
    float* out;
    if (blockIdx.z == 0)      { W = Wq; bias = bq; out = g_q; }
    else if (blockIdx.z == 1) { W = Wk; bias = bk; out = g_k; }
    else                      { W = Wv; bias = bv; out = g_v; }

    __shared__ float As[GBK][GBM + 4];   // [k][m], padded row = 68 floats (16B-aligned)
    __shared__ float Ws[GBK][GBN];       // [k][n]

    const int m0 = blockIdx.x * GBM;     // 0..4095
    const int n0 = blockIdx.y * GBN;     // 0..1023
    const int tid = threadIdx.x;
    const int tx = tid & 15;             // 0..15
    const int ty = tid >> 4;             // 0..15

    float acc[4][4];
#pragma unroll
    for (int i = 0; i < 4; i++)
#pragma unroll
        for (int j = 0; j < 4; j++) acc[i][j] = 0.f;

    // A-tile load indices: 64 rows x 16 cols, one float4 per thread
    const int ar = tid >> 2;             // 0..63
    const int ac = (tid & 3) << 2;       // 0,4,8,12
    // W-tile load indices: 16 rows x 64 cols, one float4 per thread
    const int wr = tid >> 4;             // 0..15
    const int wc = (tid & 15) << 2;      // 0..60

    for (int k0 = 0; k0 < HIDD; k0 += GBK) {
        float4 a = *(const float4*)&X[(size_t)(m0 + ar) * HIDD + k0 + ac];
        As[ac + 0][ar] = a.x;
        As[ac + 1][ar] = a.y;
        As[ac + 2][ar] = a.z;
        As[ac + 3][ar] = a.w;
        *(float4*)&Ws[wr][wc] = *(const float4*)&W[(size_t)(k0 + wr) * HIDD + n0 + wc];
        __syncthreads();

#pragma unroll
        for (int k = 0; k < GBK; k++) {
            float4 av = *(float4*)&As[k][ty << 2];
            float4 wv = *(float4*)&Ws[k][tx << 2];
            acc[0][0] += av.x * wv.x; acc[0][1] += av.x * wv.y;
            acc[0][2] += av.x * wv.z; acc[0][3] += av.x * wv.w;
            acc[1][0] += av.y * wv.x; acc[1][1] += av.y * wv.y;
            acc[1][2] += av.y * wv.z; acc[1][3] += av.y * wv.w;
            acc[2][0] += av.z * wv.x; acc[2][1] += av.z * wv.y;
            acc[2][2] += av.z * wv.z; acc[2][3] += av.z * wv.w;
            acc[3][0] += av.w * wv.x; acc[3][1] += av.w * wv.y;
            acc[3][2] += av.w * wv.z; acc[3][3] += av.w * wv.w;
        }
        __syncthreads();
    }

    // Epilogue: +bias, write blocked layout.
    // m0 is a multiple of 64 -> fixed (b, nq); n0 is a multiple of 64 -> fixed h.
    const int b  = m0 / Sseq;
    const int nq = (m0 % Sseq) / BLK;
    const int h  = n0 / BLK;
    float* obase = out + ((((size_t)b * Hh + h) * NBQ + nq) * (BLK * Dd));
    float4 bv4 = *(const float4*)&bias[n0 + (tx << 2)];
#pragma unroll
    for (int i = 0; i < 4; i++) {
        float4 v;
        v.x = acc[i][0] + bv4.x;
        v.y = acc[i][1] + bv4.y;
        v.z = acc[i][2] + bv4.z;
        v.w = acc[i][3] + bv4.w;
        *(float4*)&obase[((ty << 2) + i) * Dd + (tx << 2)] = v;
    }
}

// ---------------------------------------------------------------------------
// Sparse block attention. One CTA per (b, h, q-block). 256 threads.
// Dynamic smem: Qst[64][68] (d-major), Kst[64][68] (d-major), Vs[64][64],
//               Ss[64][512]
// ---------------------------------------------------------------------------
#define QST_OFF 0
#define KST_OFF (64 * 68)
#define VS_OFF  (KST_OFF + 64 * 68)
#define SS_OFF  (VS_OFF + 64 * 64)
#define ATTN_SMEM_FLOATS (SS_OFF + 64 * 512)
#define ATTN_SMEM_BYTES  (ATTN_SMEM_FLOATS * 4)

__global__ __launch_bounds__(256)
void attn_kernel(const float* __restrict__ mask,
                 const int* __restrict__ kidx,
                 float* __restrict__ out)
{
    extern __shared__ float sm[];
    float* Qst = sm + QST_OFF;   // [d][i], row stride 68
    float* Kst = sm + KST_OFF;   // [d][j], row stride 68
    float* Vs  = sm + VS_OFF;    // [j][d], row stride 64
    float* Ss  = sm + SS_OFF;    // [i][c], row stride 512

    const int nq = blockIdx.x;
    const int h  = blockIdx.y;
    const int b  = blockIdx.z;
    const int tid = threadIdx.x;
    const int tx = tid & 15;
    const int ty = tid >> 4;

    const size_t tile_base = (((size_t)b * Hh + h) * NBQ) * (BLK * Dd);
    const float* qsrc = g_q + tile_base + (size_t)nq * (BLK * Dd);

    // ---- load Q (transpose to d-major) ----
    for (int e = tid; e < 1024; e += 256) {
        int i  = e >> 4;            // row 0..63
        int c4 = (e & 15) << 2;     // d 0..60
        float4 qv = *(const float4*)&qsrc[i * Dd + c4];
        Qst[(c4 + 0) * 68 + i] = qv.x;
        Qst[(c4 + 1) * 68 + i] = qv.y;
        Qst[(c4 + 2) * 68 + i] = qv.z;
        Qst[(c4 + 3) * 68 + i] = qv.w;
    }

    const int* kidx_p = kidx + ((size_t)h * NBQ + nq) * KSEL;
    const int rowq0 = nq * BLK;

    // ---- scores: for each selected key block ----
    for (int kb = 0; kb < KSEL; kb++) {
        const int kv = kidx_p[kb];
        const float* ksrc = g_k + tile_base + (size_t)kv * (BLK * Dd);

        __syncthreads();   // protect Kst from previous iteration's readers
        for (int e = tid; e < 1024; e += 256) {
            int j  = e >> 4;
            int c4 = (e & 15) << 2;
            float4 kv4 = *(const float4*)&ksrc[j * Dd + c4];
            Kst[(c4 + 0) * 68 + j] = kv4.x;
            Kst[(c4 + 1) * 68 + j] = kv4.y;
            Kst[(c4 + 2) * 68 + j] = kv4.z;
            Kst[(c4 + 3) * 68 + j] = kv4.w;
        }
        __syncthreads();

        float sacc[4][4];
#pragma unroll
        for (int i = 0; i < 4; i++)
#pragma unroll
            for (int j = 0; j < 4; j++) sacc[i][j] = 0.f;

#pragma unroll 8
        for (int d = 0; d < Dd; d++) {
            float4 qv = *(float4*)&Qst[d * 68 + (ty << 2)];
            float4 kk = *(float4*)&Kst[d * 68 + (tx << 2)];
            sacc[0][0] += qv.x * kk.x; sacc[0][1] += qv.x * kk.y;
            sacc[0][2] += qv.x * kk.z; sacc[0][3] += qv.x * kk.w;
            sacc[1][0] += qv.y * kk.x; sacc[1][1] += qv.y * kk.y;
            sacc[1][2] += qv.y * kk.z; sacc[1][3] += qv.y * kk.w;
            sacc[2][0] += qv.z * kk.x; sacc[2][1] += qv.z * kk.y;
            sacc[2][2] += qv.z * kk.z; sacc[2][3] += qv.z * kk.w;
            sacc[3][0] += qv.w * kk.x; sacc[3][1] += qv.w * kk.y;
            sacc[3][2] += qv.w * kk.z; sacc[3][3] += qv.w * kk.w;
        }

        // scale * mask, store to score matrix
#pragma unroll
        for (int i = 0; i < 4; i++) {
            const int rq = rowq0 + (ty << 2) + i;
            float4 m4 = *(const float4*)&mask[(size_t)rq * Sseq + kv * BLK + (tx << 2)];
            float4 sv;
            sv.x = sacc[i][0] * 0.125f * m4.x;
            sv.y = sacc[i][1] * 0.125f * m4.y;
            sv.z = sacc[i][2] * 0.125f * m4.z;
            sv.w = sacc[i][3] * 0.125f * m4.w;
            *(float4*)&Ss[((ty << 2) + i) * 512 + kb * BLK + (tx << 2)] = sv;
        }
    }
    __syncthreads();

    // ---- softmax over 512 columns, 8 warps x 8 rows ----
    {
        const int warp = tid >> 5;
        const int lane = tid & 31;
        for (int r = warp * 8; r < warp * 8 + 8; r++) {
            float* row = &Ss[r * 512];
            float mx = -1e30f;
#pragma unroll
            for (int c = lane; c < 512; c += 32) mx = fmaxf(mx, row[c]);
#pragma unroll
            for (int off = 16; off > 0; off >>= 1)
                mx = fmaxf(mx, __shfl_xor_sync(0xFFFFFFFFu, mx, off));
            float s = 0.f;
#pragma unroll
            for (int c = lane; c < 512; c += 32) {
                float e = __expf(row[c] - mx);
                row[c] = e;
                s += e;
            }
#pragma unroll
            for (int off = 16; off > 0; off >>= 1)
                s += __shfl_xor_sync(0xFFFFFFFFu, s, off);
            float inv = 1.f / s;
#pragma unroll
            for (int c = lane; c < 512; c += 32) row[c] *= inv;
        }
    }
    __syncthreads();

    // ---- ctx = probs @ V ----
    float cacc[4][4];
#pragma unroll
    for (int i = 0; i < 4; i++)
#pragma unroll
        for (int j = 0; j < 4; j++) cacc[i][j] = 0.f;

    for (int kb = 0; kb < KSEL; kb++) {
        const int kv = kidx_p[kb];
        const float* vsrc = g_v + tile_base + (size_t)kv * (BLK * Dd);
        for (int e = tid; e < 1024; e += 256)
            *(float4*)&Vs[e << 2] = *(const float4*)&vsrc[e << 2];
        __syncthreads();

#pragma unroll 8
        for (int j = 0; j < BLK; j++) {
            float p0 = Ss[((ty << 2) + 0) * 512 + kb * BLK + j];
            float p1 = Ss[((ty << 2) + 1) * 512 + kb * BLK + j];
            float p2 = Ss[((ty << 2) + 2) * 512 + kb * BLK + j];
            float p3 = Ss[((ty << 2) + 3) * 512 + kb * BLK + j];
            float4 vv = *(float4*)&Vs[j * Dd + (tx << 2)];
            cacc[0][0] += p0 * vv.x; cacc[0][1] += p0 * vv.y;
            cacc[0][2] += p0 * vv.z; cacc[0][3] += p0 * vv.w;
            cacc[1][0] += p1 * vv.x; cacc[1][1] += p1 * vv.y;
            cacc[1][2] += p1 * vv.z; cacc[1][3] += p1 * vv.w;
            cacc[2][0] += p2 * vv.x; cacc[2][1] += p2 * vv.y;
            cacc[2][2] += p2 * vv.z; cacc[2][3] += p2 * vv.w;
            cacc[3][0] += p3 * vv.x; cacc[3][1] += p3 * vv.y;
            cacc[3][2] += p3 * vv.z; cacc[3][3] += p3 * vv.w;
        }
        __syncthreads();
    }

    // ---- write output: out[b, nq*64+i, h*64+d] ----
    float* ob = out + ((size_t)b * Sseq + nq * BLK) * HIDD + h * Dd;
#pragma unroll
    for (int i = 0; i < 4; i++) {
        *(float4*)&ob[((ty << 2) + i) * HIDD + (tx << 2)] =
            make_float4(cacc[i][0], cacc[i][1], cacc[i][2], cacc[i][3]);
    }
}

// ---------------------------------------------------------------------------
// Launch
// Inputs (metadata order): hidden_states, attention_mask, kidx,
//                          Wq, bq, Wk, bk, Wv, bv
// ---------------------------------------------------------------------------
extern "C" void kernel_launch(void* const* d_in, const int* in_sizes, int n_in,
                              void* d_out, int out_size)
{
    const float* X    = (const float*)d_in[0];
    const float* mask = (const float*)d_in[1];
    const int*   kidx = (const int*)d_in[2];
    const float* Wq   = (const float*)d_in[3];
    const float* bq   = (const float*)d_in[4];
    const float* Wk   = (const float*)d_in[5];
    const float* bk   = (const float*)d_in[6];
    const float* Wv   = (const float*)d_in[7];
    const float* bv   = (const float*)d_in[8];
    float* out = (float*)d_out;

    static bool attr_set = false;
    if (!attr_set) {
        cudaFuncSetAttribute(attn_kernel,
                             cudaFuncAttributeMaxDynamicSharedMemorySize,
                             ATTN_SMEM_BYTES);
        attr_set = true;
    }

    dim3 gemm_grid((Bsz * Sseq) / GBM, HIDD / GBN, 3);
    qkv_kernel<<<gemm_grid, 256>>>(X, Wq, bq, Wk, bk, Wv, bv);

    dim3 attn_grid(NBQ, Hh, Bsz);
    attn_kernel<<<attn_grid, 256, ATTN_SMEM_BYTES>>>(mask, kidx, out);
}

// round 3
// speedup vs baseline: 2.1335x; 2.1335x over previous
#include <cuda_runtime.h>
#include <cuda_bf16.h>
#include <math.h>

// Problem constants
#define Bsz   2
#define Sseq  2048
#define HIDD  1024
#define Hh    16
#define NBQ   32
#define KSEL  8
#define BLK   64
#define Dd    64

// Blocked scratch: (B, H, NBQ, BLK, D)
#define QKV_ELEMS (Bsz * Hh * NBQ * BLK * Dd)   // 4,194,304
__device__ float g_q[QKV_ELEMS];
__device__ float g_k[QKV_ELEMS];
__device__ float g_v[QKV_ELEMS];

// bf16 split-precision operands (16B-aligned for cp.async)
__device__ __align__(256) __nv_bfloat16 g_xhi[Bsz * Sseq * HIDD];
__device__ __align__(256) __nv_bfloat16 g_xlo[Bsz * Sseq * HIDD];
__device__ __align__(256) __nv_bfloat16 g_wthi[3 * HIDD * HIDD];   // [z][n][k]
__device__ __align__(256) __nv_bfloat16 g_wtlo[3 * HIDD * HIDD];

// ---------------------------------------------------------------------------
// Generic-PTX helpers (NO 'a'-suffix features: mma.sync / ldmatrix / cp.async)
// ---------------------------------------------------------------------------
static __device__ __forceinline__ unsigned smem_u32(const void* p) {
    unsigned a;
    asm("{ .reg .u64 t; cvta.to.shared.u64 t, %1; cvt.u32.u64 %0, t; }"
        : "=r"(a) : "l"(p));
    return a;
}

static __device__ __forceinline__ void cp16(unsigned dst, const void* src) {
    asm volatile("cp.async.cg.shared.global [%0], [%1], 16;"
                 :: "r"(dst), "l"(src));
}
static __device__ __forceinline__ void cp_commit() {
    asm volatile("cp.async.commit_group;");
}
static __device__ __forceinline__ void cp_wait1() {
    asm volatile("cp.async.wait_group 1;");
}

static __device__ __forceinline__ void ldm_x4(unsigned r[4], unsigned addr) {
    asm volatile("ldmatrix.sync.aligned.m8n8.x4.shared.b16 {%0,%1,%2,%3}, [%4];"
                 : "=r"(r[0]), "=r"(r[1]), "=r"(r[2]), "=r"(r[3]) : "r"(addr));
}

static __device__ __forceinline__ void mma16816(float c[4], const unsigned a[4],
                                                unsigned b0, unsigned b1) {
    asm volatile(
        "mma.sync.aligned.m16n8k16.row.col.f32.bf16.bf16.f32 "
        "{%0,%1,%2,%3}, {%4,%5,%6,%7}, {%8,%9}, {%0,%1,%2,%3};"
        : "+f"(c[0]), "+f"(c[1]), "+f"(c[2]), "+f"(c[3])
        : "r"(a[0]), "r"(a[1]), "r"(a[2]), "r"(a[3]), "r"(b0), "r"(b1));
}

// ---------------------------------------------------------------------------
// Conversion kernels: fp32 -> bf16 hi/lo split
// ---------------------------------------------------------------------------
__global__ __launch_bounds__(256)
void cvt_x_kernel(const float* __restrict__ X)
{
    int i4 = (blockIdx.x * 256 + threadIdx.x) << 2;
    float4 v = *(const float4*)(X + i4);
    __nv_bfloat16 h0 = __float2bfloat16(v.x);
    __nv_bfloat16 h1 = __float2bfloat16(v.y);
    __nv_bfloat16 h2 = __float2bfloat16(v.z);
    __nv_bfloat16 h3 = __float2bfloat16(v.w);
    __nv_bfloat16 l0 = __float2bfloat16(v.x - __bfloat162float(h0));
    __nv_bfloat16 l1 = __float2bfloat16(v.y - __bfloat162float(h1));
    __nv_bfloat16 l2 = __float2bfloat16(v.z - __bfloat162float(h2));
    __nv_bfloat16 l3 = __float2bfloat16(v.w - __bfloat162float(h3));
    *(__nv_bfloat162*)(g_xhi + i4)     = __halves2bfloat162(h0, h1);
    *(__nv_bfloat162*)(g_xhi + i4 + 2) = __halves2bfloat162(h2, h3);
    *(__nv_bfloat162*)(g_xlo + i4)     = __halves2bfloat162(l0, l1);
    *(__nv_bfloat162*)(g_xlo + i4 + 2) = __halves2bfloat162(l2, l3);
}

__global__ __launch_bounds__(256)
void cvt_w_kernel(const float* __restrict__ Wq, const float* __restrict__ Wk,
                  const float* __restrict__ Wv)
{
    __shared__ float t[32][33];
    const float* W = (blockIdx.z == 0) ? Wq : (blockIdx.z == 1) ? Wk : Wv;
    const int k0 = blockIdx.x * 32;
    const int n0 = blockIdx.y * 32;
    const int tx = threadIdx.x;       // 0..31
    const int ty = threadIdx.y;       // 0..7

#pragma unroll
    for (int r = 0; r < 32; r += 8)
        t[ty + r][tx] = W[(size_t)(k0 + ty + r) * HIDD + n0 + tx];
    __syncthreads();

    const size_t ob = ((size_t)blockIdx.z << 20);
#pragma unroll
    for (int r = 0; r < 32; r += 8) {
        float v = t[tx][ty + r];
        __nv_bfloat16 h = __float2bfloat16(v);
        __nv_bfloat16 l = __float2bfloat16(v - __bfloat162float(h));
        size_t o = ob + (size_t)(n0 + ty + r) * HIDD + k0 + tx;
        g_wthi[o] = h;
        g_wtlo[o] = l;
    }
}

// ---------------------------------------------------------------------------
// QKV GEMM via mma.sync bf16 split precision.
// CTA 128x128, BK=32, 8 warps (4x2), warp tile 32x64.
// Smem per stage: Ahi/Alo/Bhi/Blo, each 128 rows x 32 bf16, row stride 80B.
// ---------------------------------------------------------------------------
#define ROWB 80
#define TILE_SZ (128 * ROWB)        // 10240 B
#define STAGE_SZ (4 * TILE_SZ)      // 40960 B
#define GEMM_SMEM_BYTES (2 * STAGE_SZ)

__global__ __launch_bounds__(256, 2)
void qkv_mma_kernel(const float* __restrict__ bq, const float* __restrict__ bk,
                    const float* __restrict__ bv)
{
    extern __shared__ char sm[];
    const unsigned sbase = smem_u32(sm);
    const int tid  = threadIdx.x;
    const int lane = tid & 31;
    const int wid  = tid >> 5;
    const int m0 = blockIdx.x * 128;
    const int n0 = blockIdx.y * 128;
    const int z  = blockIdx.z;

    const __nv_bfloat16* Bhi_g = g_wthi + ((size_t)z << 20);
    const __nv_bfloat16* Blo_g = g_wtlo + ((size_t)z << 20);
    const float* bias = (z == 0) ? bq : (z == 1) ? bk : bv;
    float* out = (z == 0) ? g_q : (z == 1) ? g_k : g_v;

    const int warp_m0 = (wid & 3) * 32;
    const int warp_n0 = (wid >> 2) * 64;

    float acc[2][8][4];
#pragma unroll
    for (int i = 0; i < 2; i++)
#pragma unroll
        for (int j = 0; j < 8; j++)
#pragma unroll
            for (int l = 0; l < 4; l++) acc[i][j][l] = 0.f;

    // per-thread cp.async chunk coords (2 chunks per tile)
    const int r0 = tid >> 2,          c0 = tid & 3;
    const int r1 = (tid + 256) >> 2,  c1 = (tid + 256) & 3;

    // ldmatrix A per-thread offset: row = warp_m0 + (lane&15), +16B if lane>=16
    const unsigned aoff = (unsigned)(warp_m0 + (lane & 15)) * ROWB + ((lane >> 4) << 4);
    // B lds per-thread offset: row = warp_n0 + lane/4, byte (lane&3)*4
    const unsigned boff = (unsigned)(warp_n0 + (lane >> 2)) * ROWB + ((lane & 3) << 2);

#define ISSUE(stage, kc)                                                      \
    do {                                                                      \
        unsigned sb = sbase + (stage) * STAGE_SZ;                             \
        unsigned d0 = sb + (unsigned)r0 * ROWB + (c0 << 4);                   \
        unsigned d1 = sb + (unsigned)r1 * ROWB + (c1 << 4);                   \
        size_t ga0 = (size_t)(m0 + r0) * HIDD + (kc) + c0 * 8;                \
        size_t ga1 = (size_t)(m0 + r1) * HIDD + (kc) + c1 * 8;                \
        size_t gb0 = (size_t)(n0 + r0) * HIDD + (kc) + c0 * 8;                \
        size_t gb1 = (size_t)(n0 + r1) * HIDD + (kc) + c1 * 8;                \
        cp16(d0,               g_xhi + ga0);                                  \
        cp16(d1,               g_xhi + ga1);                                  \
        cp16(d0 + TILE_SZ,     g_xlo + ga0);                                  \
        cp16(d1 + TILE_SZ,     g_xlo + ga1);                                  \
        cp16(d0 + 2 * TILE_SZ, Bhi_g + gb0);                                  \
        cp16(d1 + 2 * TILE_SZ, Bhi_g + gb1);                                  \
        cp16(d0 + 3 * TILE_SZ, Blo_g + gb0);                                  \
        cp16(d1 + 3 * TILE_SZ, Blo_g + gb1);                                  \
    } while (0)

    ISSUE(0, 0);
    cp_commit();

    const int NCHUNK = HIDD / 32;   // 32
    for (int c = 0; c < NCHUNK; c++) {
        if (c + 1 < NCHUNK) ISSUE((c + 1) & 1, (c + 1) * 32);
        cp_commit();
        cp_wait1();
        __syncthreads();

        unsigned sb = sbase + (c & 1) * STAGE_SZ;
#pragma unroll
        for (int ks = 0; ks < 2; ks++) {
            unsigned koff = ks * 32;                 // 16 bf16 = 32 bytes
            unsigned aad = sb + aoff + koff;
            unsigned ahi0[4], ahi1[4], alo0[4], alo1[4];
            ldm_x4(ahi0, aad);
            ldm_x4(ahi1, aad + 16 * ROWB);
            ldm_x4(alo0, aad + TILE_SZ);
            ldm_x4(alo1, aad + TILE_SZ + 16 * ROWB);

            unsigned bb = sb + 2 * TILE_SZ + boff + koff;
#pragma unroll
            for (int nt = 0; nt < 8; nt++) {
                unsigned ba = bb + nt * 8 * ROWB;
                unsigned bhi0 = *(const unsigned*)(sm + (ba - sbase));
                unsigned bhi1 = *(const unsigned*)(sm + (ba - sbase) + 16);
                unsigned blo0 = *(const unsigned*)(sm + (ba - sbase) + TILE_SZ);
                unsigned blo1 = *(const unsigned*)(sm + (ba - sbase) + TILE_SZ + 16);
                mma16816(acc[0][nt], ahi0, bhi0, bhi1);
                mma16816(acc[1][nt], ahi1, bhi0, bhi1);
                mma16816(acc[0][nt], ahi0, blo0, blo1);
                mma16816(acc[1][nt], ahi1, blo0, blo1);
                mma16816(acc[0][nt], alo0, bhi0, bhi1);
                mma16816(acc[1][nt], alo1, bhi0, bhi1);
            }
        }
        __syncthreads();
    }

    // Epilogue: c frag thread mapping: rows g, g+8; cols 2c, 2c+1
    const int g  = lane >> 2;
    const int cc = lane & 3;
#pragma unroll
    for (int nt = 0; nt < 8; nt++) {
        const int N = n0 + warp_n0 + nt * 8 + cc * 2;
        const int h = N >> 6, d = N & 63;
        float2 bv2 = *(const float2*)&bias[N];
#pragma unroll
        for (int mt = 0; mt < 2; mt++) {
#pragma unroll
            for (int rr = 0; rr < 2; rr++) {
                const int M  = m0 + warp_m0 + mt * 16 + g + rr * 8;
                const int b  = M >> 11;
                const int s_ = M & 2047;
                const int nq = s_ >> 6;
                const int ii = s_ & 63;
                float* op = out + ((((size_t)b * Hh + h) * NBQ + nq) << 12)
                                + ii * Dd + d;
                float2 v;
                v.x = acc[mt][nt][rr * 2 + 0] + bv2.x;
                v.y = acc[mt][nt][rr * 2 + 1] + bv2.y;
                *(float2*)op = v;
            }
        }
    }
}

// ---------------------------------------------------------------------------
// Sparse block attention, flash-style online softmax.
// One CTA per (b, h, q-block). 256 threads. Smem ~67.6 KB -> 3 CTAs/SM.
// ---------------------------------------------------------------------------
#define AQ_OFF 0
#define AK_OFF (64 * 68)
#define AV_OFF (AK_OFF + 64 * 68)
#define AP_OFF (AV_OFF + 64 * 64)
#define ATTN_SMEM_FLOATS (AP_OFF + 64 * 64)
#define ATTN_SMEM_BYTES  (ATTN_SMEM_FLOATS * 4)

__global__ __launch_bounds__(256, 3)
void attn_kernel(const float* __restrict__ mask,
                 const int* __restrict__ kidx,
                 float* __restrict__ out)
{
    extern __shared__ float smf[];
    float* Qst = smf + AQ_OFF;   // [d][i], row stride 68
    float* Kst = smf + AK_OFF;   // [d][j], row stride 68
    float* Vs  = smf + AV_OFF;   // [j][d], row stride 64
    float* Ps  = smf + AP_OFF;   // [i][j], row stride 64

    const int nq = blockIdx.x;
    const int h  = blockIdx.y;
    const int b  = blockIdx.z;
    const int tid = threadIdx.x;
    const int tx = tid & 15;
    const int ty = tid >> 4;

    const size_t tile_base = (((size_t)b * Hh + h) * NBQ) * (BLK * Dd);
    const float* qsrc = g_q + tile_base + (size_t)nq * (BLK * Dd);

    for (int e = tid; e < 1024; e += 256) {
        int i  = e >> 4;
        int c4 = (e & 15) << 2;
        float4 qv = *(const float4*)&qsrc[i * Dd + c4];
        Qst[(c4 + 0) * 68 + i] = qv.x;
        Qst[(c4 + 1) * 68 + i] = qv.y;
        Qst[(c4 + 2) * 68 + i] = qv.z;
        Qst[(c4 + 3) * 68 + i] = qv.w;
    }

    const int* kidx_p = kidx + ((size_t)h * NBQ + nq) * KSEL;
    const int rowq0 = nq * BLK;

    float m_r[4], l_r[4], cacc[4][4];
#pragma unroll
    for (int i = 0; i < 4; i++) {
        m_r[i] = -1e30f;
        l_r[i] = 0.f;
#pragma unroll
        for (int j = 0; j < 4; j++) cacc[i][j] = 0.f;
    }

    for (int kb = 0; kb < KSEL; kb++) {
        const int kv = kidx_p[kb];
        const float* ksrc = g_k + tile_base + (size_t)kv * (BLK * Dd);
        const float* vsrc = g_v + tile_base + (size_t)kv * (BLK * Dd);

        __syncthreads();
        for (int e = tid; e < 1024; e += 256) {
            int j  = e >> 4;
            int c4 = (e & 15) << 2;
            float4 kv4 = *(const float4*)&ksrc[j * Dd + c4];
            Kst[(c4 + 0) * 68 + j] = kv4.x;
            Kst[(c4 + 1) * 68 + j] = kv4.y;
            Kst[(c4 + 2) * 68 + j] = kv4.z;
            Kst[(c4 + 3) * 68 + j] = kv4.w;
            *(float4*)&Vs[e << 2] = *(const float4*)&vsrc[e << 2];
        }
        __syncthreads();

        float sacc[4][4];
#pragma unroll
        for (int i = 0; i < 4; i++)
#pragma unroll
            for (int j = 0; j < 4; j++) sacc[i][j] = 0.f;

#pragma unroll 8
        for (int d = 0; d < Dd; d++) {
            float4 qv = *(float4*)&Qst[d * 68 + (ty << 2)];
            float4 kk = *(float4*)&Kst[d * 68 + (tx << 2)];
            sacc[0][0] += qv.x * kk.x; sacc[0][1] += qv.x * kk.y;
            sacc[0][2] += qv.x * kk.z; sacc[0][3] += qv.x * kk.w;
            sacc[1][0] += qv.y * kk.x; sacc[1][1] += qv.y * kk.y;
            sacc[1][2] += qv.y * kk.z; sacc[1][3] += qv.y * kk.w;
            sacc[2][0] += qv.z * kk.x; sacc[2][1] += qv.z * kk.y;
            sacc[2][2] += qv.z * kk.z; sacc[2][3] += qv.z * kk.w;
            sacc[3][0] += qv.w * kk.x; sacc[3][1] += qv.w * kk.y;
            sacc[3][2] += qv.w * kk.z; sacc[3][3] += qv.w * kk.w;
        }

#pragma unroll
        for (int i = 0; i < 4; i++) {
            const int rq = rowq0 + (ty << 2) + i;
            float4 m4 = *(const float4*)&mask[(size_t)rq * Sseq + kv * BLK + (tx << 2)];
            sacc[i][0] = sacc[i][0] * 0.125f * m4.x;
            sacc[i][1] = sacc[i][1] * 0.125f * m4.y;
            sacc[i][2] = sacc[i][2] * 0.125f * m4.z;
            sacc[i][3] = sacc[i][3] * 0.125f * m4.w;
        }

#pragma unroll
        for (int i = 0; i < 4; i++) {
            float rmax = fmaxf(fmaxf(sacc[i][0], sacc[i][1]),
                               fmaxf(sacc[i][2], sacc[i][3]));
#pragma unroll
            for (int off = 1; off < 16; off <<= 1)
                rmax = fmaxf(rmax, __shfl_xor_sync(0xFFFFFFFFu, rmax, off));
            float mnew = fmaxf(m_r[i], rmax);
            float f = __expf(m_r[i] - mnew);
            float p0 = __expf(sacc[i][0] - mnew);
            float p1 = __expf(sacc[i][1] - mnew);
            float p2 = __expf(sacc[i][2] - mnew);
            float p3 = __expf(sacc[i][3] - mnew);
            float rs = (p0 + p1) + (p2 + p3);
#pragma unroll
            for (int off = 1; off < 16; off <<= 1)
                rs += __shfl_xor_sync(0xFFFFFFFFu, rs, off);
            l_r[i] = l_r[i] * f + rs;
            m_r[i] = mnew;
            cacc[i][0] *= f; cacc[i][1] *= f; cacc[i][2] *= f; cacc[i][3] *= f;
            *(float4*)&Ps[((ty << 2) + i) * 64 + (tx << 2)] =
                make_float4(p0, p1, p2, p3);
        }
        __syncthreads();

#pragma unroll 8
        for (int j = 0; j < BLK; j++) {
            float p0 = Ps[((ty << 2) + 0) * 64 + j];
            float p1 = Ps[((ty << 2) + 1) * 64 + j];
            float p2 = Ps[((ty << 2) + 2) * 64 + j];
            float p3 = Ps[((ty << 2) + 3) * 64 + j];
            float4 vv = *(float4*)&Vs[j * Dd + (tx << 2)];
            cacc[0][0] += p0 * vv.x; cacc[0][1] += p0 * vv.y;
            cacc[0][2] += p0 * vv.z; cacc[0][3] += p0 * vv.w;
            cacc[1][0] += p1 * vv.x; cacc[1][1] += p1 * vv.y;
            cacc[1][2] += p1 * vv.z; cacc[1][3] += p1 * vv.w;
            cacc[2][0] += p2 * vv.x; cacc[2][1] += p2 * vv.y;
            cacc[2][2] += p2 * vv.z; cacc[2][3] += p2 * vv.w;
            cacc[3][0] += p3 * vv.x; cacc[3][1] += p3 * vv.y;
            cacc[3][2] += p3 * vv.z; cacc[3][3] += p3 * vv.w;
        }
    }

    float* ob = out + ((size_t)b * Sseq + nq * BLK) * HIDD + h * Dd;
#pragma unroll
    for (int i = 0; i < 4; i++) {
        float inv = 1.f / l_r[i];
        *(float4*)&ob[((ty << 2) + i) * HIDD + (tx << 2)] =
            make_float4(cacc[i][0] * inv, cacc[i][1] * inv,
                        cacc[i][2] * inv, cacc[i][3] * inv);
    }
}

// ---------------------------------------------------------------------------
// Launch
// ---------------------------------------------------------------------------
extern "C" void kernel_launch(void* const* d_in, const int* in_sizes, int n_in,
                              void* d_out, int out_size)
{
    const float* X    = (const float*)d_in[0];
    const float* mask = (const float*)d_in[1];
    const int*   kidx = (const int*)d_in[2];
    const float* Wq   = (const float*)d_in[3];
    const float* bq   = (const float*)d_in[4];
    const float* Wk   = (const float*)d_in[5];
    const float* bk   = (const float*)d_in[6];
    const float* Wv   = (const float*)d_in[7];
    const float* bv   = (const float*)d_in[8];
    float* out = (float*)d_out;

    static bool attr_set = false;
    if (!attr_set) {
        cudaFuncSetAttribute(attn_kernel,
                             cudaFuncAttributeMaxDynamicSharedMemorySize,
                             ATTN_SMEM_BYTES);
        cudaFuncSetAttribute(qkv_mma_kernel,
                             cudaFuncAttributeMaxDynamicSharedMemorySize,
                             GEMM_SMEM_BYTES);
        attr_set = true;
    }

    cvt_x_kernel<<<(Bsz * Sseq * HIDD) / (256 * 4), 256>>>(X);
    cvt_w_kernel<<<dim3(HIDD / 32, HIDD / 32, 3), dim3(32, 8)>>>(Wq, Wk, Wv);

    dim3 gemm_grid((Bsz * Sseq) / 128, HIDD / 128, 3);
    qkv_mma_kernel<<<gemm_grid, 256, GEMM_SMEM_BYTES>>>(bq, bk, bv);

    dim3 attn_grid(NBQ, Hh, Bsz);
    attn_kernel<<<attn_grid, 256, ATTN_SMEM_BYTES>>>(mask, kidx, out);
}

// round 4
// speedup vs baseline: 3.1155x; 1.4602x over previous
#include <cuda_runtime.h>
#include <cuda_bf16.h>
#include <math.h>

// Problem constants
#define Bsz   2
#define Sseq  2048
#define HIDD  1024
#define Hh    16
#define NBQ   32
#define KSEL  8
#define BLK   64
#define Dd    64

#define QKV_ELEMS (Bsz * Hh * NBQ * BLK * Dd)   // 4,194,304 per tensor

// bf16 split-precision GEMM inputs
__device__ __align__(256) __nv_bfloat16 g_xhi[Bsz * Sseq * HIDD];
__device__ __align__(256) __nv_bfloat16 g_xlo[Bsz * Sseq * HIDD];
__device__ __align__(256) __nv_bfloat16 g_wthi[3 * HIDD * HIDD];   // [z][n][k]
__device__ __align__(256) __nv_bfloat16 g_wtlo[3 * HIDD * HIDD];

// QKV outputs, bf16 hi/lo, layout [z][b,h,blk][row][d]
__device__ __align__(256) __nv_bfloat16 g_ohi[3 * QKV_ELEMS];
__device__ __align__(256) __nv_bfloat16 g_olo[3 * QKV_ELEMS];

// ---------------------------------------------------------------------------
// Generic-PTX helpers (portable on sm_103 family target)
// ---------------------------------------------------------------------------
static __device__ __forceinline__ unsigned smem_u32(const void* p) {
    unsigned a;
    asm("{ .reg .u64 t; cvta.to.shared.u64 t, %1; cvt.u32.u64 %0, t; }"
        : "=r"(a) : "l"(p));
    return a;
}

static __device__ __forceinline__ void cp16(unsigned dst, const void* src) {
    asm volatile("cp.async.cg.shared.global [%0], [%1], 16;"
                 :: "r"(dst), "l"(src));
}
static __device__ __forceinline__ void cp_commit() {
    asm volatile("cp.async.commit_group;");
}
static __device__ __forceinline__ void cp_wait1() {
    asm volatile("cp.async.wait_group 1;");
}
static __device__ __forceinline__ void cp_wait0() {
    asm volatile("cp.async.wait_group 0;" ::: "memory");
}

static __device__ __forceinline__ void ldm_x4(unsigned r[4], unsigned addr) {
    asm volatile("ldmatrix.sync.aligned.m8n8.x4.shared.b16 {%0,%1,%2,%3}, [%4];"
                 : "=r"(r[0]), "=r"(r[1]), "=r"(r[2]), "=r"(r[3]) : "r"(addr));
}
static __device__ __forceinline__ void ldm_x4t(unsigned r[4], unsigned addr) {
    asm volatile("ldmatrix.sync.aligned.m8n8.x4.trans.shared.b16 {%0,%1,%2,%3}, [%4];"
                 : "=r"(r[0]), "=r"(r[1]), "=r"(r[2]), "=r"(r[3]) : "r"(addr));
}

static __device__ __forceinline__ void mma16816(float c[4], const unsigned a[4],
                                                unsigned b0, unsigned b1) {
    asm volatile(
        "mma.sync.aligned.m16n8k16.row.col.f32.bf16.bf16.f32 "
        "{%0,%1,%2,%3}, {%4,%5,%6,%7}, {%8,%9}, {%0,%1,%2,%3};"
        : "+f"(c[0]), "+f"(c[1]), "+f"(c[2]), "+f"(c[3])
        : "r"(a[0]), "r"(a[1]), "r"(a[2]), "r"(a[3]), "r"(b0), "r"(b1));
}

static __device__ __forceinline__ unsigned b2u(__nv_bfloat162 v) {
    return *reinterpret_cast<unsigned*>(&v);
}

// ---------------------------------------------------------------------------
// Conversion kernels: fp32 -> bf16 hi/lo split
// ---------------------------------------------------------------------------
__global__ __launch_bounds__(256)
void cvt_x_kernel(const float* __restrict__ X)
{
    int i4 = (blockIdx.x * 256 + threadIdx.x) << 2;
    float4 v = *(const float4*)(X + i4);
    __nv_bfloat16 h0 = __float2bfloat16(v.x);
    __nv_bfloat16 h1 = __float2bfloat16(v.y);
    __nv_bfloat16 h2 = __float2bfloat16(v.z);
    __nv_bfloat16 h3 = __float2bfloat16(v.w);
    __nv_bfloat16 l0 = __float2bfloat16(v.x - __bfloat162float(h0));
    __nv_bfloat16 l1 = __float2bfloat16(v.y - __bfloat162float(h1));
    __nv_bfloat16 l2 = __float2bfloat16(v.z - __bfloat162float(h2));
    __nv_bfloat16 l3 = __float2bfloat16(v.w - __bfloat162float(h3));
    *(__nv_bfloat162*)(g_xhi + i4)     = __halves2bfloat162(h0, h1);
    *(__nv_bfloat162*)(g_xhi + i4 + 2) = __halves2bfloat162(h2, h3);
    *(__nv_bfloat162*)(g_xlo + i4)     = __halves2bfloat162(l0, l1);
    *(__nv_bfloat162*)(g_xlo + i4 + 2) = __halves2bfloat162(l2, l3);
}

__global__ __launch_bounds__(256)
void cvt_w_kernel(const float* __restrict__ Wq, const float* __restrict__ Wk,
                  const float* __restrict__ Wv)
{
    __shared__ float t[32][33];
    const float* W = (blockIdx.z == 0) ? Wq : (blockIdx.z == 1) ? Wk : Wv;
    const int k0 = blockIdx.x * 32;
    const int n0 = blockIdx.y * 32;
    const int tx = threadIdx.x;
    const int ty = threadIdx.y;

#pragma unroll
    for (int r = 0; r < 32; r += 8)
        t[ty + r][tx] = W[(size_t)(k0 + ty + r) * HIDD + n0 + tx];
    __syncthreads();

    const size_t ob = ((size_t)blockIdx.z << 20);
#pragma unroll
    for (int r = 0; r < 32; r += 8) {
        float v = t[tx][ty + r];
        __nv_bfloat16 h = __float2bfloat16(v);
        __nv_bfloat16 l = __float2bfloat16(v - __bfloat162float(h));
        size_t o = ob + (size_t)(n0 + ty + r) * HIDD + k0 + tx;
        g_wthi[o] = h;
        g_wtlo[o] = l;
    }
}

// ---------------------------------------------------------------------------
// QKV GEMM via mma.sync bf16 split precision. CTA 128x128, BK=32, 8 warps.
// Epilogue writes bf16 hi/lo into blocked (b,h,blk,row,d) layout.
// ---------------------------------------------------------------------------
#define ROWB 80
#define TILE_SZ (128 * ROWB)
#define STAGE_SZ (4 * TILE_SZ)
#define GEMM_SMEM_BYTES (2 * STAGE_SZ)

__global__ __launch_bounds__(256, 2)
void qkv_mma_kernel(const float* __restrict__ bq, const float* __restrict__ bk,
                    const float* __restrict__ bv)
{
    extern __shared__ char sm[];
    const unsigned sbase = smem_u32(sm);
    const int tid  = threadIdx.x;
    const int lane = tid & 31;
    const int wid  = tid >> 5;
    const int m0 = blockIdx.x * 128;
    const int n0 = blockIdx.y * 128;
    const int z  = blockIdx.z;

    const __nv_bfloat16* Bhi_g = g_wthi + ((size_t)z << 20);
    const __nv_bfloat16* Blo_g = g_wtlo + ((size_t)z << 20);
    const float* bias = (z == 0) ? bq : (z == 1) ? bk : bv;
    __nv_bfloat16* ohi = g_ohi + (size_t)z * QKV_ELEMS;
    __nv_bfloat16* olo = g_olo + (size_t)z * QKV_ELEMS;

    const int warp_m0 = (wid & 3) * 32;
    const int warp_n0 = (wid >> 2) * 64;

    float acc[2][8][4];
#pragma unroll
    for (int i = 0; i < 2; i++)
#pragma unroll
        for (int j = 0; j < 8; j++)
#pragma unroll
            for (int l = 0; l < 4; l++) acc[i][j][l] = 0.f;

    const int r0 = tid >> 2,          c0 = tid & 3;
    const int r1 = (tid + 256) >> 2,  c1 = (tid + 256) & 3;

    const unsigned aoff = (unsigned)(warp_m0 + (lane & 15)) * ROWB + ((lane >> 4) << 4);
    const unsigned boff = (unsigned)(warp_n0 + (lane >> 2)) * ROWB + ((lane & 3) << 2);

#define ISSUE(stage, kc)                                                      \
    do {                                                                      \
        unsigned sb = sbase + (stage) * STAGE_SZ;                             \
        unsigned d0 = sb + (unsigned)r0 * ROWB + (c0 << 4);                   \
        unsigned d1 = sb + (unsigned)r1 * ROWB + (c1 << 4);                   \
        size_t ga0 = (size_t)(m0 + r0) * HIDD + (kc) + c0 * 8;                \
        size_t ga1 = (size_t)(m0 + r1) * HIDD + (kc) + c1 * 8;                \
        size_t gb0 = (size_t)(n0 + r0) * HIDD + (kc) + c0 * 8;                \
        size_t gb1 = (size_t)(n0 + r1) * HIDD + (kc) + c1 * 8;                \
        cp16(d0,               g_xhi + ga0);                                  \
        cp16(d1,               g_xhi + ga1);                                  \
        cp16(d0 + TILE_SZ,     g_xlo + ga0);                                  \
        cp16(d1 + TILE_SZ,     g_xlo + ga1);                                  \
        cp16(d0 + 2 * TILE_SZ, Bhi_g + gb0);                                  \
        cp16(d1 + 2 * TILE_SZ, Bhi_g + gb1);                                  \
        cp16(d0 + 3 * TILE_SZ, Blo_g + gb0);                                  \
        cp16(d1 + 3 * TILE_SZ, Blo_g + gb1);                                  \
    } while (0)

    ISSUE(0, 0);
    cp_commit();

    const int NCHUNK = HIDD / 32;
    for (int c = 0; c < NCHUNK; c++) {
        if (c + 1 < NCHUNK) ISSUE((c + 1) & 1, (c + 1) * 32);
        cp_commit();
        cp_wait1();
        __syncthreads();

        unsigned sb = sbase + (c & 1) * STAGE_SZ;
#pragma unroll
        for (int ks = 0; ks < 2; ks++) {
            unsigned koff = ks * 32;
            unsigned aad = sb + aoff + koff;
            unsigned ahi0[4], ahi1[4], alo0[4], alo1[4];
            ldm_x4(ahi0, aad);
            ldm_x4(ahi1, aad + 16 * ROWB);
            ldm_x4(alo0, aad + TILE_SZ);
            ldm_x4(alo1, aad + TILE_SZ + 16 * ROWB);

            unsigned bb = sb + 2 * TILE_SZ + boff + koff;
#pragma unroll
            for (int nt = 0; nt < 8; nt++) {
                unsigned ba = bb + nt * 8 * ROWB;
                unsigned bhi0 = *(const unsigned*)(sm + (ba - sbase));
                unsigned bhi1 = *(const unsigned*)(sm + (ba - sbase) + 16);
                unsigned blo0 = *(const unsigned*)(sm + (ba - sbase) + TILE_SZ);
                unsigned blo1 = *(const unsigned*)(sm + (ba - sbase) + TILE_SZ + 16);
                mma16816(acc[0][nt], ahi0, bhi0, bhi1);
                mma16816(acc[1][nt], ahi1, bhi0, bhi1);
                mma16816(acc[0][nt], ahi0, blo0, blo1);
                mma16816(acc[1][nt], ahi1, blo0, blo1);
                mma16816(acc[0][nt], alo0, bhi0, bhi1);
                mma16816(acc[1][nt], alo1, bhi0, bhi1);
            }
        }
        __syncthreads();
    }

    const int g  = lane >> 2;
    const int cc = lane & 3;
#pragma unroll
    for (int nt = 0; nt < 8; nt++) {
        const int N = n0 + warp_n0 + nt * 8 + cc * 2;
        const int h = N >> 6, d = N & 63;
        float2 bv2 = *(const float2*)&bias[N];
#pragma unroll
        for (int mt = 0; mt < 2; mt++) {
#pragma unroll
            for (int rr = 0; rr < 2; rr++) {
                const int M  = m0 + warp_m0 + mt * 16 + g + rr * 8;
                const int b  = M >> 11;
                const int s_ = M & 2047;
                const int nq = s_ >> 6;
                const int ii = s_ & 63;
                size_t idx = ((((size_t)b * Hh + h) * NBQ + nq) << 12) + ii * Dd + d;
                float vx = acc[mt][nt][rr * 2 + 0] + bv2.x;
                float vy = acc[mt][nt][rr * 2 + 1] + bv2.y;
                __nv_bfloat16 hx = __float2bfloat16(vx);
                __nv_bfloat16 hy = __float2bfloat16(vy);
                *(__nv_bfloat162*)(ohi + idx) = __halves2bfloat162(hx, hy);
                *(__nv_bfloat162*)(olo + idx) = __halves2bfloat162(
                    __float2bfloat16(vx - __bfloat162float(hx)),
                    __float2bfloat16(vy - __bfloat162float(hy)));
            }
        }
    }
}

// ---------------------------------------------------------------------------
// Tensor-core flash attention. 1 CTA per (b,h,nq): 128 threads (4 warps),
// each warp owns 16 q-rows x all 64 cols; 8 key blocks sequentially.
// Smem: Q hi/lo + K hi/lo + V hi/lo tiles (XOR-swizzled 64x64 bf16) = 48 KB.
// ---------------------------------------------------------------------------
#define ASQH 0
#define ASQL 8192
#define ASKH 16384
#define ASKL 24576
#define ASVH 32768
#define ASVL 40960
#define ATTN_SMEM_BYTES 49152

static __device__ __forceinline__ unsigned swz(int r, int c16) {
    return (unsigned)((r << 7) + ((c16 ^ (r & 7)) << 4));
}

__global__ __launch_bounds__(128)
void attn_mma_kernel(const float* __restrict__ mask,
                     const int* __restrict__ kidx,
                     float* __restrict__ out)
{
    extern __shared__ char sm[];
    const unsigned sb = smem_u32(sm);
    const int nq = blockIdx.x, h = blockIdx.y, b = blockIdx.z;
    const int tid = threadIdx.x, lane = tid & 31, wid = tid >> 5;
    const int g = lane >> 2, c = lane & 3;
    const int qq = lane >> 3, rl = lane & 7;
    const int wm0 = wid * 16;

    const size_t tbase = (((size_t)b * Hh + h) * NBQ) << 12;
    const __nv_bfloat16* qhi = g_ohi + tbase + ((size_t)nq << 12);
    const __nv_bfloat16* qlo = g_olo + tbase + ((size_t)nq << 12);
    const __nv_bfloat16* khb = g_ohi + QKV_ELEMS + tbase;
    const __nv_bfloat16* klb = g_olo + QKV_ELEMS + tbase;
    const __nv_bfloat16* vhb = g_ohi + 2 * (size_t)QKV_ELEMS + tbase;
    const __nv_bfloat16* vlb = g_olo + 2 * (size_t)QKV_ELEMS + tbase;

    int kvi[KSEL];
    const int* kp = kidx + (h * NBQ + nq) * KSEL;
#pragma unroll
    for (int i = 0; i < KSEL; i++) kvi[i] = kp[i];

    // prologue: Q + KV(kb=0), one commit group
#pragma unroll
    for (int j = 0; j < 4; j++) {
        int ch = tid + j * 128;
        int r = ch >> 3, cc16 = ch & 7;
        unsigned o = swz(r, cc16);
        int go = r * 64 + cc16 * 8;
        cp16(sb + ASQH + o, qhi + go);
        cp16(sb + ASQL + o, qlo + go);
    }
    {
        size_t kvo = (size_t)kvi[0] << 12;
#pragma unroll
        for (int j = 0; j < 4; j++) {
            int ch = tid + j * 128;
            int r = ch >> 3, cc16 = ch & 7;
            unsigned o = swz(r, cc16);
            size_t go = kvo + r * 64 + cc16 * 8;
            cp16(sb + ASKH + o, khb + go);
            cp16(sb + ASKL + o, klb + go);
            cp16(sb + ASVH + o, vhb + go);
            cp16(sb + ASVL + o, vlb + go);
        }
    }
    cp_commit();

    float o_acc[8][4];
#pragma unroll
    for (int t = 0; t < 8; t++)
#pragma unroll
        for (int j = 0; j < 4; j++) o_acc[t][j] = 0.f;
    float mrow0 = -1e30f, mrow1 = -1e30f, lrow0 = 0.f, lrow1 = 0.f;

    const int rq0 = nq * BLK + wm0 + g;
    const float* mk0 = mask + (size_t)rq0 * Sseq;
    const float* mk1 = mk0 + 8 * Sseq;

    for (int kb = 0; kb < KSEL; kb++) {
        cp_wait0();
        __syncthreads();

        // ---- scores S = Q K^T (split bf16, 3 passes) ----
        float s[8][4];
#pragma unroll
        for (int t = 0; t < 8; t++)
#pragma unroll
            for (int j = 0; j < 4; j++) s[t][j] = 0.f;

#pragma unroll
        for (int ks = 0; ks < 4; ks++) {
            unsigned ahi[4], alo[4];
            unsigned qa = swz(wm0 + (lane & 15), 2 * ks + (lane >> 4));
            ldm_x4(ahi, sb + ASQH + qa);
            ldm_x4(alo, sb + ASQL + qa);
#pragma unroll
            for (int tp = 0; tp < 4; tp++) {
                unsigned bh[4], bl[4];
                unsigned ka = swz(tp * 16 + rl + ((qq >> 1) << 3), 2 * ks + (qq & 1));
                ldm_x4(bh, sb + ASKH + ka);
                ldm_x4(bl, sb + ASKL + ka);
                mma16816(s[2 * tp],     ahi, bh[0], bh[1]);
                mma16816(s[2 * tp + 1], ahi, bh[2], bh[3]);
                mma16816(s[2 * tp],     ahi, bl[0], bl[1]);
                mma16816(s[2 * tp + 1], ahi, bl[2], bl[3]);
                mma16816(s[2 * tp],     alo, bh[0], bh[1]);
                mma16816(s[2 * tp + 1], alo, bh[2], bh[3]);
            }
        }

        // ---- scale * mask ----
        const int kv64 = kvi[kb] * BLK;
#pragma unroll
        for (int t = 0; t < 8; t++) {
            float2 m0 = *(const float2*)&mk0[kv64 + 8 * t + 2 * c];
            float2 m1 = *(const float2*)&mk1[kv64 + 8 * t + 2 * c];
            s[t][0] *= 0.125f * m0.x;  s[t][1] *= 0.125f * m0.y;
            s[t][2] *= 0.125f * m1.x;  s[t][3] *= 0.125f * m1.y;
        }

        // ---- online softmax (rows g and g+8 of this warp's strip) ----
        float r0 = -1e30f, r1 = -1e30f;
#pragma unroll
        for (int t = 0; t < 8; t++) {
            r0 = fmaxf(r0, fmaxf(s[t][0], s[t][1]));
            r1 = fmaxf(r1, fmaxf(s[t][2], s[t][3]));
        }
        r0 = fmaxf(r0, __shfl_xor_sync(0xFFFFFFFFu, r0, 1));
        r0 = fmaxf(r0, __shfl_xor_sync(0xFFFFFFFFu, r0, 2));
        r1 = fmaxf(r1, __shfl_xor_sync(0xFFFFFFFFu, r1, 1));
        r1 = fmaxf(r1, __shfl_xor_sync(0xFFFFFFFFu, r1, 2));
        float mn0 = fmaxf(mrow0, r0), mn1 = fmaxf(mrow1, r1);
        float f0 = __expf(mrow0 - mn0), f1 = __expf(mrow1 - mn1);
        float rs0 = 0.f, rs1 = 0.f;
#pragma unroll
        for (int t = 0; t < 8; t++) {
            s[t][0] = __expf(s[t][0] - mn0);
            s[t][1] = __expf(s[t][1] - mn0);
            s[t][2] = __expf(s[t][2] - mn1);
            s[t][3] = __expf(s[t][3] - mn1);
            rs0 += s[t][0] + s[t][1];
            rs1 += s[t][2] + s[t][3];
        }
        rs0 += __shfl_xor_sync(0xFFFFFFFFu, rs0, 1);
        rs0 += __shfl_xor_sync(0xFFFFFFFFu, rs0, 2);
        rs1 += __shfl_xor_sync(0xFFFFFFFFu, rs1, 1);
        rs1 += __shfl_xor_sync(0xFFFFFFFFu, rs1, 2);
        lrow0 = lrow0 * f0 + rs0;
        lrow1 = lrow1 * f1 + rs1;
        mrow0 = mn0; mrow1 = mn1;
#pragma unroll
        for (int t = 0; t < 8; t++) {
            o_acc[t][0] *= f0; o_acc[t][1] *= f0;
            o_acc[t][2] *= f1; o_acc[t][3] *= f1;
        }

        // ---- O += P V (P from registers, split bf16, 3 passes) ----
#pragma unroll
        for (int ks = 0; ks < 4; ks++) {
            unsigned phi[4], plo[4];
#pragma unroll
            for (int hf = 0; hf < 2; hf++) {
                float p0 = s[2 * ks + hf][0], p1 = s[2 * ks + hf][1];
                float p2 = s[2 * ks + hf][2], p3 = s[2 * ks + hf][3];
                __nv_bfloat16 h0 = __float2bfloat16(p0), h1 = __float2bfloat16(p1);
                __nv_bfloat16 h2 = __float2bfloat16(p2), h3 = __float2bfloat16(p3);
                phi[2 * hf + 0] = b2u(__halves2bfloat162(h0, h1));
                phi[2 * hf + 1] = b2u(__halves2bfloat162(h2, h3));
                plo[2 * hf + 0] = b2u(__halves2bfloat162(
                    __float2bfloat16(p0 - __bfloat162float(h0)),
                    __float2bfloat16(p1 - __bfloat162float(h1))));
                plo[2 * hf + 1] = b2u(__halves2bfloat162(
                    __float2bfloat16(p2 - __bfloat162float(h2)),
                    __float2bfloat16(p3 - __bfloat162float(h3))));
            }
#pragma unroll
            for (int tp = 0; tp < 4; tp++) {
                unsigned vh[4], vl[4];
                unsigned va = swz(16 * ks + rl + ((qq & 1) << 3), 2 * tp + (qq >> 1));
                ldm_x4t(vh, sb + ASVH + va);
                ldm_x4t(vl, sb + ASVL + va);
                mma16816(o_acc[2 * tp],     phi, vh[0], vh[1]);
                mma16816(o_acc[2 * tp + 1], phi, vh[2], vh[3]);
                mma16816(o_acc[2 * tp],     phi, vl[0], vl[1]);
                mma16816(o_acc[2 * tp + 1], phi, vl[2], vl[3]);
                mma16816(o_acc[2 * tp],     plo, vh[0], vh[1]);
                mma16816(o_acc[2 * tp + 1], plo, vh[2], vh[3]);
            }
        }

        __syncthreads();
        if (kb + 1 < KSEL) {
            size_t kvo = (size_t)kvi[kb + 1] << 12;
#pragma unroll
            for (int j = 0; j < 4; j++) {
                int ch = tid + j * 128;
                int r = ch >> 3, cc16 = ch & 7;
                unsigned o = swz(r, cc16);
                size_t go = kvo + r * 64 + cc16 * 8;
                cp16(sb + ASKH + o, khb + go);
                cp16(sb + ASKL + o, klb + go);
                cp16(sb + ASVH + o, vhb + go);
                cp16(sb + ASVL + o, vlb + go);
            }
            cp_commit();
        }
    }

    // ---- normalize + write out[b, nq*64+row, h*64+d] ----
    float i0 = 1.f / lrow0, i1 = 1.f / lrow1;
    float* o0 = out + ((size_t)b * Sseq + rq0) * HIDD + h * Dd;
    float* o1 = o0 + 8 * HIDD;
#pragma unroll
    for (int t = 0; t < 8; t++) {
        *(float2*)&o0[8 * t + 2 * c] = make_float2(o_acc[t][0] * i0, o_acc[t][1] * i0);
        *(float2*)&o1[8 * t + 2 * c] = make_float2(o_acc[t][2] * i1, o_acc[t][3] * i1);
    }
}

// ---------------------------------------------------------------------------
// Launch
// ---------------------------------------------------------------------------
extern "C" void kernel_launch(void* const* d_in, const int* in_sizes, int n_in,
                              void* d_out, int out_size)
{
    const float* X    = (const float*)d_in[0];
    const float* mask = (const float*)d_in[1];
    const int*   kidx = (const int*)d_in[2];
    const float* Wq   = (const float*)d_in[3];
    const float* bq   = (const float*)d_in[4];
    const float* Wk   = (const float*)d_in[5];
    const float* bk   = (const float*)d_in[6];
    const float* Wv   = (const float*)d_in[7];
    const float* bv   = (const float*)d_in[8];
    float* out = (float*)d_out;

    static bool attr_set = false;
    if (!attr_set) {
        cudaFuncSetAttribute(qkv_mma_kernel,
                             cudaFuncAttributeMaxDynamicSharedMemorySize,
                             GEMM_SMEM_BYTES);
        cudaFuncSetAttribute(attn_mma_kernel,
                             cudaFuncAttributeMaxDynamicSharedMemorySize,
                             ATTN_SMEM_BYTES);
        attr_set = true;
    }

    cvt_x_kernel<<<(Bsz * Sseq * HIDD) / (256 * 4), 256>>>(X);
    cvt_w_kernel<<<dim3(HIDD / 32, HIDD / 32, 3), dim3(32, 8)>>>(Wq, Wk, Wv);

    dim3 gemm_grid((Bsz * Sseq) / 128, HIDD / 128, 3);
    qkv_mma_kernel<<<gemm_grid, 256, GEMM_SMEM_BYTES>>>(bq, bk, bv);

    dim3 attn_grid(NBQ, Hh, Bsz);
    attn_mma_kernel<<<attn_grid, 128, ATTN_SMEM_BYTES>>>(mask, kidx, out);
}